// round 10
// baseline (speedup 1.0000x reference)
#include <cuda_runtime.h>
#include <cuda_bf16.h>
#include <cstdint>

// HyperedgeMeanAggregator: out[h,:] = mean_{e: seg_ids[e]==h} embed_table[node_idx[e],:]
// seg_ids SORTED, indices int32 (JAX x64 off).
//
// Segment-ownership (warp owns 4 hyperedges; binary search gives entry range;
// plain STG, no atomics/memset) + cp.async.cg SMEM ring pipeline (DEPTH=8) so
// gather latency is covered by ~196KB of in-flight bytes per SM instead of
// register-resident MLP.

#define FEAT    128
#define FEAT4   (FEAT / 4)     // 32 float4 per row = one warp
#define SEGW    4              // segments per warp
#define BLOCK   256            // 8 warps per block
#define WARPS   (BLOCK / 32)
#define DEPTH   8              // pipeline depth (ring slots per warp)

__device__ __forceinline__ int lbound(const int* __restrict__ a, int n, int key) {
    int lo = 0, hi = n;
    while (lo < hi) {
        int mid = (lo + hi) >> 1;
        if (__ldg(&a[mid]) < key) lo = mid + 1; else hi = mid;
    }
    return lo;
}

__device__ __forceinline__ void cp_async16(unsigned int smem_dst, const void* gsrc) {
    asm volatile("cp.async.cg.shared.global [%0], [%1], 16;"
                 :: "r"(smem_dst), "l"(gsrc));
}
__device__ __forceinline__ void cp_commit() {
    asm volatile("cp.async.commit_group;");
}
template <int N>
__device__ __forceinline__ void cp_wait() {
    asm volatile("cp.async.wait_group %0;" :: "n"(N));
}

__global__ __launch_bounds__(BLOCK)
void agg_kernel(const float* __restrict__ table,
                const int* __restrict__ node_idx,
                const int* __restrict__ seg_ids,
                float* __restrict__ out,
                int E, int H) {
    __shared__ float4 ring[WARPS][DEPTH][FEAT4];   // 8 * 8 * 512B = 32KB

    int wid   = threadIdx.x >> 5;
    int lane  = threadIdx.x & 31;
    int gwarp = blockIdx.x * WARPS + wid;

    int h_lo = gwarp * SEGW;
    if (h_lo >= H) return;
    int h_hi = h_lo + SEGW; if (h_hi > H) h_hi = H;

    int eb = lbound(seg_ids, E, h_lo);
    int ee = lbound(seg_ids, E, h_hi);

    const float4* t4 = reinterpret_cast<const float4*>(table);
    float4* o4 = reinterpret_cast<float4*>(out);
    const float4 zero = make_float4(0.f, 0.f, 0.f, 0.f);

    unsigned int ring_base =
        (unsigned int)__cvta_generic_to_shared(&ring[wid][0][lane]);
    // slot s address = ring_base + s * 512

    // ---- prologue: issue first DEPTH entries ----
    #pragma unroll
    for (int k = 0; k < DEPTH; ++k) {
        int e = eb + k;
        if (e < ee) {
            unsigned int n = (unsigned int)__ldg(&node_idx[e]);
            cp_async16(ring_base + (unsigned int)k * (FEAT4 * 16),
                       t4 + (size_t)n * FEAT4 + lane);
        }
        cp_commit();   // commit even if empty: keeps group<->entry mapping exact
    }

    float4 acc = zero;
    float  cnt = 0.f;
    int prev = h_lo - 1;
    int cur  = (eb < ee) ? __ldg(&seg_ids[eb]) : -1;

#define FLUSH()                                                        \
    do {                                                               \
        for (int h = prev + 1; h < cur; ++h)                           \
            o4[(unsigned int)h * FEAT4 + lane] = zero;                 \
        float inv = 1.0f / cnt;                                        \
        o4[(unsigned int)cur * FEAT4 + lane] =                         \
            make_float4(acc.x * inv, acc.y * inv, acc.z * inv, acc.w * inv); \
        prev = cur;                                                    \
    } while (0)

    for (int e = eb; e < ee; ++e) {
        cp_wait<DEPTH - 1>();   // entry e's group complete
        int slot = (e - eb) & (DEPTH - 1);
        float4 v = ring[wid][slot][lane];          // LDS.128, conflict-free
        int s = __ldg(&seg_ids[e]);

        // refill this slot with entry e+DEPTH (LDS above already executed)
        int ei = e + DEPTH;
        if (ei < ee) {
            unsigned int n = (unsigned int)__ldg(&node_idx[ei]);
            cp_async16(ring_base + (unsigned int)slot * (FEAT4 * 16),
                       t4 + (size_t)n * FEAT4 + lane);
        }
        cp_commit();

        if (s != cur) { FLUSH(); acc = zero; cnt = 0.f; cur = s; }
        acc.x += v.x; acc.y += v.y; acc.z += v.z; acc.w += v.w;
        cnt += 1.f;
    }

    if (cur >= 0) FLUSH();
    for (int h = prev + 1; h < h_hi; ++h)          // trailing empty segments
        o4[(unsigned int)h * FEAT4 + lane] = zero;
#undef FLUSH

    cp_wait<0>();   // drain any speculative groups before exit
}

extern "C" void kernel_launch(void* const* d_in, const int* in_sizes, int n_in,
                              void* d_out, int out_size) {
    const float* table    = (const float*)d_in[0];
    const int*   node_idx = (const int*)d_in[1];
    const int*   seg_ids  = (const int*)d_in[2];
    float*       out      = (float*)d_out;

    int E = in_sizes[1];
    int H = out_size / FEAT;

    int warps  = (H + SEGW - 1) / SEGW;
    int blocks = (warps + WARPS - 1) / WARPS;
    agg_kernel<<<blocks, BLOCK>>>(table, node_idx, seg_ids, out, E, H);
}